// round 9
// baseline (speedup 1.0000x reference)
#include <cuda_runtime.h>
#include <cuda_fp16.h>

#define NN 100000
#define NE 3200000
#define PAD 32
#define CSRCAP (NE + PAD * NN)

// Scratch (static __device__ allocations — zero-initialized at load;
// k_l2 restores d_cnt to zero so graph replays start clean)
__device__ int    d_cnt[NN + 1];     // in-degree counts; [NN] = segment cursor
__device__ float  d_dinv[NN];        // rsqrt(deg+1)
__device__ int    d_off[NN];         // padded CSR segment base per col
__device__ int    d_cur[NN];         // fill cursors
__device__ int2   d_csr2[CSRCAP];    // {row, float_bits(dinv[row])}, 32-aligned segments
__device__ __half d_xh[NN * 16];     // x in fp16
__device__ __half d_h1h[NN * 32];    // h1 in fp16

// ---------------------------------------------------------------------------
// histogram of col; 4 edges per thread via int4
__global__ void k_deg(const int4* __restrict__ eic4, int E4, int n) {
    int e = blockIdx.x * blockDim.x + threadIdx.x;
    if (e >= E4) return;
    int4 c = eic4[e];
    if ((unsigned)c.x >= (unsigned)n) c.x = 0;
    if ((unsigned)c.y >= (unsigned)n) c.y = 0;
    if ((unsigned)c.z >= (unsigned)n) c.z = 0;
    if ((unsigned)c.w >= (unsigned)n) c.w = 0;
    atomicAdd(&d_cnt[c.x], 1);
    atomicAdd(&d_cnt[c.y], 1);
    atomicAdd(&d_cnt[c.z], 1);
    atomicAdd(&d_cnt[c.w], 1);
}

// segment base via global cursor (order-free), 32-entry padded;
// zero-fills pad slots; fused dinv + x->fp16 convert
__global__ void k_base(const float4* __restrict__ x4, int n) {
    int i = blockIdx.x * blockDim.x + threadIdx.x;
    if (i >= n) return;
    int c = d_cnt[i];
    int cp = (c + PAD - 1) & ~(PAD - 1);
    int b = atomicAdd(&d_cnt[NN], cp);
    d_off[i] = b;
    d_cur[i] = b;
    d_dinv[i] = rsqrtf((float)c + 1.0f);
    int2 z = make_int2(0, 0);           // row 0, nm = 0.0f -> contributes nothing
    for (int j = c; j < cp; j++) d_csr2[b + j] = z;
    float4 a0 = x4[(size_t)i * 4 + 0];
    float4 a1 = x4[(size_t)i * 4 + 1];
    float4 a2 = x4[(size_t)i * 4 + 2];
    float4 a3 = x4[(size_t)i * 4 + 3];
    __half2* dst = (__half2*)(d_xh + (size_t)i * 16);
    dst[0] = __floats2half2_rn(a0.x, a0.y);
    dst[1] = __floats2half2_rn(a0.z, a0.w);
    dst[2] = __floats2half2_rn(a1.x, a1.y);
    dst[3] = __floats2half2_rn(a1.z, a1.w);
    dst[4] = __floats2half2_rn(a2.x, a2.y);
    dst[5] = __floats2half2_rn(a2.z, a2.w);
    dst[6] = __floats2half2_rn(a3.x, a3.y);
    dst[7] = __floats2half2_rn(a3.z, a3.w);
}

// counting-sort fill, 4 edges per thread; single packed 8B store per edge
__global__ void k_fill(const int4* __restrict__ eir4,
                       const int4* __restrict__ eic4, int E4, int n) {
    int e = blockIdx.x * blockDim.x + threadIdx.x;
    if (e >= E4) return;
    int4 r = eir4[e];
    int4 c = eic4[e];
    if ((unsigned)r.x >= (unsigned)n) r.x = 0;
    if ((unsigned)r.y >= (unsigned)n) r.y = 0;
    if ((unsigned)r.z >= (unsigned)n) r.z = 0;
    if ((unsigned)r.w >= (unsigned)n) r.w = 0;
    if ((unsigned)c.x >= (unsigned)n) c.x = 0;
    if ((unsigned)c.y >= (unsigned)n) c.y = 0;
    if ((unsigned)c.z >= (unsigned)n) c.z = 0;
    if ((unsigned)c.w >= (unsigned)n) c.w = 0;
    int p0 = atomicAdd(&d_cur[c.x], 1);
    int p1 = atomicAdd(&d_cur[c.y], 1);
    int p2 = atomicAdd(&d_cur[c.z], 1);
    int p3 = atomicAdd(&d_cur[c.w], 1);
    d_csr2[p0] = make_int2(r.x, __float_as_int(d_dinv[r.x]));
    d_csr2[p1] = make_int2(r.y, __float_as_int(d_dinv[r.y]));
    d_csr2[p2] = make_int2(r.z, __float_as_int(d_dinv[r.z]));
    d_csr2[p3] = make_int2(r.w, __float_as_int(d_dinv[r.w]));
}

// ---------------------------------------------------------------------------
// Fused layer 1: gather-aggregate fp16 x (16 dims) + GEMV 16->32 + ReLU
// warp/node; lane = (edge-pair slot lane>>1) x (16B chunk q = lane&1)
// int4 index load = 2 packed edges; 32 edges per iteration, no tail
__global__ void k_l1(const float* __restrict__ W1,
                     const float* __restrict__ b1, int n) {
    __shared__ float sW[16 * 32];
    __shared__ float sb[32];
    __shared__ float sAgg[8][16];
    int tid = threadIdx.x;
    for (int j = tid; j < 512; j += blockDim.x) sW[j] = W1[j];
    if (tid < 32) sb[tid] = b1[tid];
    __syncthreads();

    int gw = (blockIdx.x * blockDim.x + tid) >> 5;
    int lane = tid & 31;
    int warp = tid >> 5;
    if (gw >= n) return;

    int s2 = (lane >> 1) * 2;   // edge-pair start within 32-edge tile
    int q = lane & 1;           // 2 uint4 chunks (8 halfs each)
    int beg = d_off[gw];
    int cnt = d_cnt[gw];
    int cp = (cnt + PAD - 1) & ~(PAD - 1);
    float dc = d_dinv[gw];
    const uint4* xh4 = (const uint4*)d_xh;

    float a[8] = {0.f, 0.f, 0.f, 0.f, 0.f, 0.f, 0.f, 0.f};
    float b[8] = {0.f, 0.f, 0.f, 0.f, 0.f, 0.f, 0.f, 0.f};
    for (int i = beg; i < beg + cp; i += 32) {
        int4 e = *(const int4*)&d_csr2[i + s2];
        uint4 v0 = xh4[(size_t)e.x * 2 + q];
        uint4 v1 = xh4[(size_t)e.z * 2 + q];
        float n0 = __int_as_float(e.y), n1 = __int_as_float(e.w);
        const __half2* h0 = (const __half2*)&v0;
        const __half2* h1 = (const __half2*)&v1;
#pragma unroll
        for (int j = 0; j < 4; j++) {
            float2 f0 = __half22float2(h0[j]);
            float2 f1 = __half22float2(h1[j]);
            a[2 * j]     += n0 * f0.x;
            a[2 * j + 1] += n0 * f0.y;
            b[2 * j]     += n1 * f1.x;
            b[2 * j + 1] += n1 * f1.y;
        }
    }
#pragma unroll
    for (int j = 0; j < 8; j++) a[j] += b[j];

    // fold edge slots (lane bits 1..4)
#pragma unroll
    for (int m = 2; m <= 16; m <<= 1) {
#pragma unroll
        for (int j = 0; j < 8; j++)
            a[j] += __shfl_xor_sync(0xffffffffu, a[j], m);
    }
    if (lane < 2) {             // lane0: dims 0-7, lane1: dims 8-15
#pragma unroll
        for (int j = 0; j < 8; j++) sAgg[warp][q * 8 + j] = a[j];
    }
    __syncwarp();

    float v = 0.f;
    if (lane < 16)
        v = dc * sAgg[warp][lane]
          + dc * dc * __half2float(d_xh[(size_t)gw * 16 + lane]);

    float o = sb[lane];
#pragma unroll
    for (int k = 0; k < 16; k++)
        o += __shfl_sync(0xffffffffu, v, k) * sW[k * 32 + lane];
    d_h1h[(size_t)gw * 32 + lane] = __float2half(fmaxf(o, 0.f));
}

// Fused layer 2 + MLP tail: gather-aggregate fp16 h1 (32 dims),
// GEMV W2+ReLU, GEMV Wl1+ReLU, dot Wl4 -> out; restores d_cnt to 0.
// warp/node; lane = (edge-pair slot lane>>2) x (16B chunk q = lane&3)
__global__ void k_l2(const float* __restrict__ W2, const float* __restrict__ b2,
                     const float* __restrict__ Wl1, const float* __restrict__ bl1,
                     const float* __restrict__ Wl4, const float* __restrict__ bl4,
                     float* __restrict__ out, int n) {
    __shared__ float sW2[1024];
    __shared__ float sWl1[1024];
    __shared__ float sb2[32], sbl1[32], sWl4[32];
    __shared__ float sAgg[8][32];
    int tid = threadIdx.x;
    for (int j = tid; j < 1024; j += blockDim.x) {
        sW2[j] = W2[j];
        sWl1[j] = Wl1[j];
    }
    if (tid < 32) { sb2[tid] = b2[tid]; sbl1[tid] = bl1[tid]; sWl4[tid] = Wl4[tid]; }
    __syncthreads();

    int gw = (blockIdx.x * blockDim.x + tid) >> 5;
    int lane = tid & 31;
    int warp = tid >> 5;
    if (gw >= n) return;

    int s2 = (lane >> 2) * 2;   // edge-pair start within 16-edge tile
    int q = lane & 3;           // 4 uint4 chunks (8 halfs each)
    int beg = d_off[gw];
    int cnt = d_cnt[gw];
    int cp = (cnt + PAD - 1) & ~(PAD - 1);
    float dc = d_dinv[gw];
    const uint4* h1h4 = (const uint4*)d_h1h;

    // restore for next graph replay (value already consumed)
    if (lane == 0) d_cnt[gw] = 0;
    if (gw == 0 && lane == 1) d_cnt[NN] = 0;

    float a[8] = {0.f, 0.f, 0.f, 0.f, 0.f, 0.f, 0.f, 0.f};
    float b[8] = {0.f, 0.f, 0.f, 0.f, 0.f, 0.f, 0.f, 0.f};
    for (int i = beg; i < beg + cp; i += 16) {
        int4 e = *(const int4*)&d_csr2[i + s2];
        uint4 v0 = h1h4[(size_t)e.x * 4 + q];
        uint4 v1 = h1h4[(size_t)e.z * 4 + q];
        float n0 = __int_as_float(e.y), n1 = __int_as_float(e.w);
        const __half2* h0 = (const __half2*)&v0;
        const __half2* h1 = (const __half2*)&v1;
#pragma unroll
        for (int j = 0; j < 4; j++) {
            float2 f0 = __half22float2(h0[j]);
            float2 f1 = __half22float2(h1[j]);
            a[2 * j]     += n0 * f0.x;
            a[2 * j + 1] += n0 * f0.y;
            b[2 * j]     += n1 * f1.x;
            b[2 * j + 1] += n1 * f1.y;
        }
    }
#pragma unroll
    for (int j = 0; j < 8; j++) a[j] += b[j];

    // fold edge slots (lane bits 2..4)
#pragma unroll
    for (int m = 4; m <= 16; m <<= 1) {
#pragma unroll
        for (int j = 0; j < 8; j++)
            a[j] += __shfl_xor_sync(0xffffffffu, a[j], m);
    }
    if (lane < 4) {             // lane q holds dims q*8 .. q*8+7
#pragma unroll
        for (int j = 0; j < 8; j++) sAgg[warp][q * 8 + j] = a[j];
    }
    __syncwarp();

    float selfh = __half2float(d_h1h[(size_t)gw * 32 + lane]);
    float v = dc * sAgg[warp][lane] + dc * dc * selfh;

    float a2 = sb2[lane];
#pragma unroll
    for (int k = 0; k < 32; k++)
        a2 += __shfl_sync(0xffffffffu, v, k) * sW2[k * 32 + lane];
    float h2 = fmaxf(a2, 0.f);

    float a3 = sbl1[lane];
#pragma unroll
    for (int k = 0; k < 32; k++)
        a3 += __shfl_sync(0xffffffffu, h2, k) * sWl1[k * 32 + lane];
    float h3 = fmaxf(a3, 0.f);

    float p = h3 * sWl4[lane];
#pragma unroll
    for (int o = 16; o > 0; o >>= 1) p += __shfl_xor_sync(0xffffffffu, p, o);
    if (lane == 0) out[gw] = p + bl4[0];
}

// ---------------------------------------------------------------------------
extern "C" void kernel_launch(void* const* d_in, const int* in_sizes, int n_in,
                              void* d_out, int out_size) {
    // Runtime input resolution by element count.
    const float* x = 0; const int* ei = 0;
    const float *W1 = 0, *b1 = 0, *W2 = 0, *b2 = 0, *Wl1 = 0, *bl1 = 0, *Wl4 = 0, *bl4 = 0;

    bool alpha = (n_in > 0 && in_sizes[0] == 512);  // alphabetical puts W1 first
    int n1024 = 0, n32 = 0;
    for (int i = 0; i < n_in; i++) {
        int s = in_sizes[i];
        const void* p = d_in[i];
        if (s == 1600000)      x  = (const float*)p;
        else if (s == 6400000) ei = (const int*)p;
        else if (s == 512)     W1 = (const float*)p;
        else if (s == 1)       bl4 = (const float*)p;
        else if (s == 1024) {
            if (n1024 == 0) W2 = (const float*)p; else Wl1 = (const float*)p;
            n1024++;
        } else if (s == 32) {
            if (alpha) {
                if      (n32 == 0) Wl4 = (const float*)p;
                else if (n32 == 1) b1  = (const float*)p;
                else if (n32 == 2) b2  = (const float*)p;
                else               bl1 = (const float*)p;
            } else {
                if      (n32 == 0) b1  = (const float*)p;
                else if (n32 == 1) b2  = (const float*)p;
                else if (n32 == 2) bl1 = (const float*)p;
                else               Wl4 = (const float*)p;
            }
            n32++;
        }
    }
    float* out = (float*)d_out;

    int n = NN;
    int E = NE;
    int E4 = E / 4;

    const int TB = 256;
    int nodeBlocks = (n + TB - 1) / TB;
    int e4Blocks = (E4 + TB - 1) / TB;
    int warpNodeBlocks = (n * 32 + TB - 1) / TB;

    const int4* eir4 = (const int4*)ei;             // rows half
    const int4* eic4 = (const int4*)(ei + E);       // cols half

    k_deg<<<e4Blocks, TB>>>(eic4, E4, n);
    k_base<<<nodeBlocks, TB>>>((const float4*)x, n);
    k_fill<<<e4Blocks, TB>>>(eir4, eic4, E4, n);
    k_l1<<<warpNodeBlocks, TB>>>(W1, b1, n);
    k_l2<<<warpNodeBlocks, TB>>>(W2, b2, Wl1, bl1, Wl4, bl4, out, n);
}

// round 10
// speedup vs baseline: 1.2277x; 1.2277x over previous
#include <cuda_runtime.h>
#include <cuda_fp16.h>

#define NN 100000
#define NE 3200000
#define NBLK ((NN + 255) / 256)   // 391 scan blocks

// Scratch (static __device__ allocations — allowed)
__device__ int    d_cnt[NN];       // in-degree counts (no self loop)
__device__ float  d_dinv[NN];      // rsqrt(deg+1)
__device__ int    d_off[NN + 1];   // CSR offsets by col
__device__ int    d_cur[NN];       // fill cursors
__device__ int    d_bsum[NBLK];    // scan block sums
__device__ int2   d_csr2[NE];      // {row, float_bits(dinv[row])} grouped by col
__device__ __half d_xh[NN * 16];   // x in fp16
__device__ __half d_h1h[NN * 32];  // h1 in fp16

// ---------------------------------------------------------------------------
// histogram of col; 4 edges per thread via int4
__global__ void k_deg(const int4* __restrict__ eic4, int E4, int n) {
    int e = blockIdx.x * blockDim.x + threadIdx.x;
    if (e >= E4) return;
    int4 c = eic4[e];
    if ((unsigned)c.x >= (unsigned)n) c.x = 0;
    if ((unsigned)c.y >= (unsigned)n) c.y = 0;
    if ((unsigned)c.z >= (unsigned)n) c.z = 0;
    if ((unsigned)c.w >= (unsigned)n) c.w = 0;
    atomicAdd(&d_cnt[c.x], 1);
    atomicAdd(&d_cnt[c.y], 1);
    atomicAdd(&d_cnt[c.z], 1);
    atomicAdd(&d_cnt[c.w], 1);
}

// ---- exclusive scan over d_cnt -> d_off (warp-shuffle) + fused dinv ----
__global__ void k_scanA(int n) {
    __shared__ int ws[8];
    int t = threadIdx.x;
    int i = blockIdx.x * 256 + t;
    int lane = t & 31, w = t >> 5;
    int v = (i < n) ? d_cnt[i] : 0;
    int s = v;
#pragma unroll
    for (int o = 1; o < 32; o <<= 1) {
        int a = __shfl_up_sync(0xffffffffu, s, o);
        if (lane >= o) s += a;
    }
    if (lane == 31) ws[w] = s;
    __syncthreads();
    if (t < 8) {
        int a = ws[t];
#pragma unroll
        for (int o = 1; o < 8; o <<= 1) {
            int b = __shfl_up_sync(0xffu, a, o);
            if (t >= o) a += b;
        }
        ws[t] = a;
    }
    __syncthreads();
    int base = w ? ws[w - 1] : 0;
    int incl = base + s;
    if (i < n) {
        d_off[i] = incl - v;                 // exclusive within block
        d_dinv[i] = rsqrtf((float)v + 1.0f); // fused dinv
    }
    if (t == 255) d_bsum[blockIdx.x] = incl;
}

// scan of 391 block sums
__global__ void k_scanB(int nb) {
    __shared__ int ws[16];
    int t = threadIdx.x;
    int lane = t & 31, w = t >> 5;
    int v = (t < nb) ? d_bsum[t] : 0;
    int s = v;
#pragma unroll
    for (int o = 1; o < 32; o <<= 1) {
        int a = __shfl_up_sync(0xffffffffu, s, o);
        if (lane >= o) s += a;
    }
    if (lane == 31) ws[w] = s;
    __syncthreads();
    if (t < 16) {
        int a = ws[t];
#pragma unroll
        for (int o = 1; o < 16; o <<= 1) {
            int b = __shfl_up_sync(0xffffu, a, o);
            if (t >= o) a += b;
        }
        ws[t] = a;
    }
    __syncthreads();
    int base = w ? ws[w - 1] : 0;
    if (t < nb) d_bsum[t] = base + s - v;    // exclusive block offsets
}

// finalize offsets/cursors + fused x -> fp16 conversion
__global__ void k_scanC(const float4* __restrict__ x4, int n, int E) {
    int i = blockIdx.x * blockDim.x + threadIdx.x;
    if (i < n) {
        int o = d_off[i] + d_bsum[i >> 8];
        d_off[i] = o;
        d_cur[i] = o;
        float4 a0 = x4[(size_t)i * 4 + 0];
        float4 a1 = x4[(size_t)i * 4 + 1];
        float4 a2 = x4[(size_t)i * 4 + 2];
        float4 a3 = x4[(size_t)i * 4 + 3];
        __half2* dst = (__half2*)(d_xh + (size_t)i * 16);
        dst[0] = __floats2half2_rn(a0.x, a0.y);
        dst[1] = __floats2half2_rn(a0.z, a0.w);
        dst[2] = __floats2half2_rn(a1.x, a1.y);
        dst[3] = __floats2half2_rn(a1.z, a1.w);
        dst[4] = __floats2half2_rn(a2.x, a2.y);
        dst[5] = __floats2half2_rn(a2.z, a2.w);
        dst[6] = __floats2half2_rn(a3.x, a3.y);
        dst[7] = __floats2half2_rn(a3.z, a3.w);
    }
    if (i == 0) d_off[n] = E;
}

// counting-sort fill, 4 edges per thread; single packed 8B store per edge
__global__ void k_fill(const int4* __restrict__ eir4,
                       const int4* __restrict__ eic4, int E4, int n) {
    int e = blockIdx.x * blockDim.x + threadIdx.x;
    if (e >= E4) return;
    int4 r = eir4[e];
    int4 c = eic4[e];
    if ((unsigned)r.x >= (unsigned)n) r.x = 0;
    if ((unsigned)r.y >= (unsigned)n) r.y = 0;
    if ((unsigned)r.z >= (unsigned)n) r.z = 0;
    if ((unsigned)r.w >= (unsigned)n) r.w = 0;
    if ((unsigned)c.x >= (unsigned)n) c.x = 0;
    if ((unsigned)c.y >= (unsigned)n) c.y = 0;
    if ((unsigned)c.z >= (unsigned)n) c.z = 0;
    if ((unsigned)c.w >= (unsigned)n) c.w = 0;
    int p0 = atomicAdd(&d_cur[c.x], 1);
    int p1 = atomicAdd(&d_cur[c.y], 1);
    int p2 = atomicAdd(&d_cur[c.z], 1);
    int p3 = atomicAdd(&d_cur[c.w], 1);
    d_csr2[p0] = make_int2(r.x, __float_as_int(d_dinv[r.x]));
    d_csr2[p1] = make_int2(r.y, __float_as_int(d_dinv[r.y]));
    d_csr2[p2] = make_int2(r.z, __float_as_int(d_dinv[r.z]));
    d_csr2[p3] = make_int2(r.w, __float_as_int(d_dinv[r.w]));
}

// ---------------------------------------------------------------------------
// Fused layer 1: gather-aggregate fp16 x (16 dims) + GEMV 16->32 + ReLU
// warp/node, 128-thread blocks (4 nodes/block) for finer CTA scheduling.
// lane = (edge slot s = lane>>1) x (16B chunk q = lane&1): 16 edges in flight
__global__ void __launch_bounds__(128)
k_l1(const float* __restrict__ W1, const float* __restrict__ b1, int n) {
    __shared__ float sW[16 * 32];
    __shared__ float sb[32];
    __shared__ float sAgg[4][16];
    int tid = threadIdx.x;
    for (int j = tid; j < 512; j += blockDim.x) sW[j] = W1[j];
    if (tid < 32) sb[tid] = b1[tid];
    __syncthreads();

    int gw = (blockIdx.x * blockDim.x + tid) >> 5;
    int lane = tid & 31;
    int warp = tid >> 5;
    if (gw >= n) return;

    int s = lane >> 1;       // 16 edge slots
    int q = lane & 1;        // 2 uint4 chunks (8 halfs each)
    int beg = d_off[gw], end = d_off[gw + 1];
    float dc = d_dinv[gw];
    const uint4* xh4 = (const uint4*)d_xh;

    float a[8] = {0.f, 0.f, 0.f, 0.f, 0.f, 0.f, 0.f, 0.f};
    for (int i = beg + s; i < end; i += 16) {
        int2 e = d_csr2[i];
        uint4 vv = xh4[(size_t)e.x * 2 + q];
        float nm = __int_as_float(e.y);
        const __half2* h = (const __half2*)&vv;
#pragma unroll
        for (int j = 0; j < 4; j++) {
            float2 f = __half22float2(h[j]);
            a[2 * j]     += nm * f.x;
            a[2 * j + 1] += nm * f.y;
        }
    }
    // fold edge slots (lane bits 1..4)
#pragma unroll
    for (int m = 2; m <= 16; m <<= 1) {
#pragma unroll
        for (int j = 0; j < 8; j++)
            a[j] += __shfl_xor_sync(0xffffffffu, a[j], m);
    }
    if (lane < 2) {          // lane0: dims 0-7, lane1: dims 8-15
#pragma unroll
        for (int j = 0; j < 8; j++) sAgg[warp][q * 8 + j] = a[j];
    }
    __syncwarp();

    float v = 0.f;
    if (lane < 16)
        v = dc * sAgg[warp][lane]
          + dc * dc * __half2float(d_xh[(size_t)gw * 16 + lane]);

    float o = sb[lane];
#pragma unroll
    for (int k = 0; k < 16; k++)
        o += __shfl_sync(0xffffffffu, v, k) * sW[k * 32 + lane];
    d_h1h[(size_t)gw * 32 + lane] = __float2half(fmaxf(o, 0.f));
}

// Fused layer 2 + MLP tail. warp/node, 128-thread blocks.
// lane = (slot s = lane>>2) x (16B chunk q = lane&3), 2-chain software pipeline
__global__ void __launch_bounds__(128)
k_l2(const float* __restrict__ W2, const float* __restrict__ b2,
     const float* __restrict__ Wl1, const float* __restrict__ bl1,
     const float* __restrict__ Wl4, const float* __restrict__ bl4,
     float* __restrict__ out, int n) {
    __shared__ float sW2[1024];
    __shared__ float sWl1[1024];
    __shared__ float sb2[32], sbl1[32], sWl4[32];
    __shared__ float sAgg[4][32];
    int tid = threadIdx.x;
    for (int j = tid; j < 1024; j += blockDim.x) {
        sW2[j] = W2[j];
        sWl1[j] = Wl1[j];
    }
    if (tid < 32) { sb2[tid] = b2[tid]; sbl1[tid] = bl1[tid]; sWl4[tid] = Wl4[tid]; }
    __syncthreads();

    int gw = (blockIdx.x * blockDim.x + tid) >> 5;
    int lane = tid & 31;
    int warp = tid >> 5;
    if (gw >= n) return;

    int s = lane >> 2;       // 8 edge slots
    int q = lane & 3;        // 4 uint4 chunks (8 halfs each)
    int beg = d_off[gw], end = d_off[gw + 1];
    float dc = d_dinv[gw];
    const uint4* h1h4 = (const uint4*)d_h1h;

    float a[8] = {0.f, 0.f, 0.f, 0.f, 0.f, 0.f, 0.f, 0.f};
    float b[8] = {0.f, 0.f, 0.f, 0.f, 0.f, 0.f, 0.f, 0.f};
    int i = beg + s;
    for (; i + 8 < end; i += 16) {
        int2 e0 = d_csr2[i];
        int2 e1 = d_csr2[i + 8];
        uint4 v0 = h1h4[(size_t)e0.x * 4 + q];
        uint4 v1 = h1h4[(size_t)e1.x * 4 + q];
        float n0 = __int_as_float(e0.y), n1 = __int_as_float(e1.y);
        const __half2* h0 = (const __half2*)&v0;
        const __half2* h1 = (const __half2*)&v1;
#pragma unroll
        for (int j = 0; j < 4; j++) {
            float2 f0 = __half22float2(h0[j]);
            float2 f1 = __half22float2(h1[j]);
            a[2 * j]     += n0 * f0.x;
            a[2 * j + 1] += n0 * f0.y;
            b[2 * j]     += n1 * f1.x;
            b[2 * j + 1] += n1 * f1.y;
        }
    }
    if (i < end) {
        int2 e0 = d_csr2[i];
        uint4 v0 = h1h4[(size_t)e0.x * 4 + q];
        float n0 = __int_as_float(e0.y);
        const __half2* h0 = (const __half2*)&v0;
#pragma unroll
        for (int j = 0; j < 4; j++) {
            float2 f0 = __half22float2(h0[j]);
            a[2 * j]     += n0 * f0.x;
            a[2 * j + 1] += n0 * f0.y;
        }
    }
#pragma unroll
    for (int j = 0; j < 8; j++) a[j] += b[j];

    // fold edge slots (lane bits 2..4)
#pragma unroll
    for (int m = 4; m <= 16; m <<= 1) {
#pragma unroll
        for (int j = 0; j < 8; j++)
            a[j] += __shfl_xor_sync(0xffffffffu, a[j], m);
    }
    if (lane < 4) {          // lane q holds dims q*8 .. q*8+7
#pragma unroll
        for (int j = 0; j < 8; j++) sAgg[warp][q * 8 + j] = a[j];
    }
    __syncwarp();

    float selfh = __half2float(d_h1h[(size_t)gw * 32 + lane]);
    float v = dc * sAgg[warp][lane] + dc * dc * selfh;

    float a2 = sb2[lane];
#pragma unroll
    for (int k = 0; k < 32; k++)
        a2 += __shfl_sync(0xffffffffu, v, k) * sW2[k * 32 + lane];
    float h2 = fmaxf(a2, 0.f);

    float a3 = sbl1[lane];
#pragma unroll
    for (int k = 0; k < 32; k++)
        a3 += __shfl_sync(0xffffffffu, h2, k) * sWl1[k * 32 + lane];
    float h3 = fmaxf(a3, 0.f);

    float p = h3 * sWl4[lane];
#pragma unroll
    for (int o = 16; o > 0; o >>= 1) p += __shfl_xor_sync(0xffffffffu, p, o);
    if (lane == 0) out[gw] = p + bl4[0];
}

// ---------------------------------------------------------------------------
extern "C" void kernel_launch(void* const* d_in, const int* in_sizes, int n_in,
                              void* d_out, int out_size) {
    // Runtime input resolution by element count.
    const float* x = 0; const int* ei = 0;
    const float *W1 = 0, *b1 = 0, *W2 = 0, *b2 = 0, *Wl1 = 0, *bl1 = 0, *Wl4 = 0, *bl4 = 0;

    bool alpha = (n_in > 0 && in_sizes[0] == 512);  // alphabetical puts W1 first
    int n1024 = 0, n32 = 0;
    for (int i = 0; i < n_in; i++) {
        int s = in_sizes[i];
        const void* p = d_in[i];
        if (s == 1600000)      x  = (const float*)p;
        else if (s == 6400000) ei = (const int*)p;
        else if (s == 512)     W1 = (const float*)p;
        else if (s == 1)       bl4 = (const float*)p;
        else if (s == 1024) {
            if (n1024 == 0) W2 = (const float*)p; else Wl1 = (const float*)p;
            n1024++;
        } else if (s == 32) {
            if (alpha) {
                if      (n32 == 0) Wl4 = (const float*)p;
                else if (n32 == 1) b1  = (const float*)p;
                else if (n32 == 2) b2  = (const float*)p;
                else               bl1 = (const float*)p;
            } else {
                if      (n32 == 0) b1  = (const float*)p;
                else if (n32 == 1) b2  = (const float*)p;
                else if (n32 == 2) bl1 = (const float*)p;
                else               Wl4 = (const float*)p;
            }
            n32++;
        }
    }
    float* out = (float*)d_out;

    int n = NN;
    int E = NE;
    int E4 = E / 4;

    const int TB = 256;
    int nodeBlocks = (n + TB - 1) / TB;
    int e4Blocks = (E4 + TB - 1) / TB;
    int warpNodeBlocks128 = (n * 32 + 127) / 128;

    void* cntPtr = 0;
    cudaGetSymbolAddress(&cntPtr, d_cnt);
    cudaMemsetAsync(cntPtr, 0, NN * sizeof(int), 0);

    const int4* eir4 = (const int4*)ei;             // rows half
    const int4* eic4 = (const int4*)(ei + E);       // cols half

    k_deg<<<e4Blocks, TB>>>(eic4, E4, n);
    k_scanA<<<nodeBlocks, TB>>>(n);
    k_scanB<<<1, 512>>>(NBLK);
    k_scanC<<<nodeBlocks, TB>>>((const float4*)x, n, E);
    k_fill<<<e4Blocks, TB>>>(eir4, eic4, E4, n);
    k_l1<<<warpNodeBlocks128, 128>>>(W1, b1, n);
    k_l2<<<warpNodeBlocks128, 128>>>(W2, b2, Wl1, bl1, Wl4, bl4, out, n);
}

// round 12
// speedup vs baseline: 1.2734x; 1.0372x over previous
#include <cuda_runtime.h>
#include <cuda_bf16.h>

#define NN 100000
#define NE 3200000
#define NBLK ((NN + 255) / 256)   // 391 scan blocks

// Scratch (static __device__ allocations — zero-init at load; scanA re-zeroes
// d_cnt each replay so the graph is replay-clean without a memset launch)
__device__ int   d_cnt[NN];        // in-degree counts (no self loop)
__device__ float d_dinv[NN];       // rsqrt(deg+1)
__device__ int   d_off[NN + 1];    // CSR offsets by col
__device__ int   d_cur[NN];        // fill cursors
__device__ int   d_bsum[NBLK];     // scan block sums
__device__ int2  d_csr2[NE];       // {row, float_bits(dinv[row])} grouped by col
__device__ float d_h1[NN * 32];

// ---------------------------------------------------------------------------
// histogram of col; 4 edges per thread via int4
__global__ void k_deg(const int4* __restrict__ eic4, int E4, int n) {
    int e = blockIdx.x * blockDim.x + threadIdx.x;
    if (e >= E4) return;
    int4 c = eic4[e];
    if ((unsigned)c.x >= (unsigned)n) c.x = 0;
    if ((unsigned)c.y >= (unsigned)n) c.y = 0;
    if ((unsigned)c.z >= (unsigned)n) c.z = 0;
    if ((unsigned)c.w >= (unsigned)n) c.w = 0;
    atomicAdd(&d_cnt[c.x], 1);
    atomicAdd(&d_cnt[c.y], 1);
    atomicAdd(&d_cnt[c.z], 1);
    atomicAdd(&d_cnt[c.w], 1);
}

// ---- per-block exclusive scan + block sums; zeroes d_cnt for next replay ----
__global__ void k_scanA(int n) {
    __shared__ int ws[8];
    int t = threadIdx.x;
    int i = blockIdx.x * 256 + t;
    int lane = t & 31, w = t >> 5;
    int v = 0;
    if (i < n) {
        v = d_cnt[i];
        d_cnt[i] = 0;                        // replay-clean without memset
    }
    int s = v;
#pragma unroll
    for (int o = 1; o < 32; o <<= 1) {
        int a = __shfl_up_sync(0xffffffffu, s, o);
        if (lane >= o) s += a;
    }
    if (lane == 31) ws[w] = s;
    __syncthreads();
    if (t < 8) {
        int a = ws[t];
#pragma unroll
        for (int o = 1; o < 8; o <<= 1) {
            int b = __shfl_up_sync(0xffu, a, o);
            if (t >= o) a += b;
        }
        ws[t] = a;
    }
    __syncthreads();
    int base = w ? ws[w - 1] : 0;
    int incl = base + s;
    if (i < n) {
        d_off[i] = incl - v;                 // exclusive within block
        d_dinv[i] = rsqrtf((float)v + 1.0f); // fused dinv
    }
    if (t == 255) d_bsum[blockIdx.x] = incl;
}

// finalize: each block redundantly sums d_bsum[j < bid] (no separate scanB).
// Block-wide broadcast of the reduced base goes through shared memory.
__global__ void k_scanC(int n, int E) {
    __shared__ int red[8];
    __shared__ int sbase;
    int t = threadIdx.x;
    int bid = blockIdx.x;
    int lane = t & 31, w = t >> 5;

    int partial = 0;
    for (int j = t; j < bid; j += 256) partial += d_bsum[j];
#pragma unroll
    for (int o = 16; o > 0; o >>= 1)
        partial += __shfl_xor_sync(0xffffffffu, partial, o);
    if (lane == 0) red[w] = partial;
    __syncthreads();
    if (t == 0) {
        int b = 0;
#pragma unroll
        for (int j = 0; j < 8; j++) b += red[j];
        sbase = b;
    }
    __syncthreads();
    int base = sbase;

    int i = bid * 256 + t;
    if (i < n) {
        int o = d_off[i] + base;
        d_off[i] = o;
        d_cur[i] = o;
    }
    if (i == 0) d_off[n] = E;
}

// counting-sort fill, 4 edges per thread; single packed 8B store per edge
__global__ void k_fill(const int4* __restrict__ eir4,
                       const int4* __restrict__ eic4, int E4, int n) {
    int e = blockIdx.x * blockDim.x + threadIdx.x;
    if (e >= E4) return;
    int4 r = eir4[e];
    int4 c = eic4[e];
    if ((unsigned)r.x >= (unsigned)n) r.x = 0;
    if ((unsigned)r.y >= (unsigned)n) r.y = 0;
    if ((unsigned)r.z >= (unsigned)n) r.z = 0;
    if ((unsigned)r.w >= (unsigned)n) r.w = 0;
    if ((unsigned)c.x >= (unsigned)n) c.x = 0;
    if ((unsigned)c.y >= (unsigned)n) c.y = 0;
    if ((unsigned)c.z >= (unsigned)n) c.z = 0;
    if ((unsigned)c.w >= (unsigned)n) c.w = 0;
    int p0 = atomicAdd(&d_cur[c.x], 1);
    int p1 = atomicAdd(&d_cur[c.y], 1);
    int p2 = atomicAdd(&d_cur[c.z], 1);
    int p3 = atomicAdd(&d_cur[c.w], 1);
    d_csr2[p0] = make_int2(r.x, __float_as_int(d_dinv[r.x]));
    d_csr2[p1] = make_int2(r.y, __float_as_int(d_dinv[r.y]));
    d_csr2[p2] = make_int2(r.z, __float_as_int(d_dinv[r.z]));
    d_csr2[p3] = make_int2(r.w, __float_as_int(d_dinv[r.w]));
}

// ---------------------------------------------------------------------------
// Fused layer 1: gather-aggregate x (16 dims) + GEMV 16->32 + ReLU
// warp/node; lane = (edge slot s = lane>>2) x (float4 chunk q = lane&3)
// software-pipelined 2 chains -> 16 edges in flight per warp
__global__ void k_l1(const float4* __restrict__ x4,
                     const float* __restrict__ x,
                     const float* __restrict__ W1,
                     const float* __restrict__ b1, int n) {
    __shared__ float sW[16 * 32];
    __shared__ float sb[32];
    int tid = threadIdx.x;
    for (int j = tid; j < 512; j += blockDim.x) sW[j] = W1[j];
    if (tid < 32) sb[tid] = b1[tid];
    __syncthreads();

    int gw = (blockIdx.x * blockDim.x + tid) >> 5;
    int lane = tid & 31;
    if (gw >= n) return;

    int s = lane >> 2;       // 8 edge slots
    int q = lane & 3;        // 4 float4 chunks = 16 dims
    int beg = d_off[gw], end = d_off[gw + 1];
    float dc = d_dinv[gw];

    float4 a0 = make_float4(0.f, 0.f, 0.f, 0.f);
    float4 a1 = make_float4(0.f, 0.f, 0.f, 0.f);
    int i = beg + s;
    for (; i + 8 < end; i += 16) {
        int2 e0 = d_csr2[i];
        int2 e1 = d_csr2[i + 8];
        float4 v0 = x4[(size_t)e0.x * 4 + q];
        float4 v1 = x4[(size_t)e1.x * 4 + q];
        float n0 = __int_as_float(e0.y), n1 = __int_as_float(e1.y);
        a0.x += n0 * v0.x; a0.y += n0 * v0.y; a0.z += n0 * v0.z; a0.w += n0 * v0.w;
        a1.x += n1 * v1.x; a1.y += n1 * v1.y; a1.z += n1 * v1.z; a1.w += n1 * v1.w;
    }
    if (i < end) {
        int2 e0 = d_csr2[i];
        float4 v0 = x4[(size_t)e0.x * 4 + q];
        float n0 = __int_as_float(e0.y);
        a0.x += n0 * v0.x; a0.y += n0 * v0.y; a0.z += n0 * v0.z; a0.w += n0 * v0.w;
    }
    float4 acc = make_float4(a0.x + a1.x, a0.y + a1.y, a0.z + a1.z, a0.w + a1.w);

    // fold edge slots (bits 2,3,4 of lane)
#pragma unroll
    for (int m = 4; m <= 16; m <<= 1) {
        acc.x += __shfl_xor_sync(0xffffffffu, acc.x, m);
        acc.y += __shfl_xor_sync(0xffffffffu, acc.y, m);
        acc.z += __shfl_xor_sync(0xffffffffu, acc.z, m);
        acc.w += __shfl_xor_sync(0xffffffffu, acc.w, m);
    }
    // redistribute: lane d (<16) takes comp d&3 of chunk d>>2
    int src = lane >> 2;
    float c0 = __shfl_sync(0xffffffffu, acc.x, src);
    float c1 = __shfl_sync(0xffffffffu, acc.y, src);
    float c2 = __shfl_sync(0xffffffffu, acc.z, src);
    float c3 = __shfl_sync(0xffffffffu, acc.w, src);
    int cc = lane & 3;
    float agg = (cc == 0) ? c0 : (cc == 1) ? c1 : (cc == 2) ? c2 : c3;

    float v = 0.f;
    if (lane < 16)
        v = dc * agg + dc * dc * x[(size_t)gw * 16 + lane];

    float o = sb[lane];
#pragma unroll
    for (int k = 0; k < 16; k++)
        o += __shfl_sync(0xffffffffu, v, k) * sW[k * 32 + lane];
    d_h1[(size_t)gw * 32 + lane] = fmaxf(o, 0.f);
}

// Fused layer 2 + MLP tail. warp/node; lane = (slot s = lane>>3) x (chunk q = lane&7)
// software-pipelined 2 chains -> 8 edges in flight per warp
__global__ void k_l2(const float* __restrict__ W2, const float* __restrict__ b2,
                     const float* __restrict__ Wl1, const float* __restrict__ bl1,
                     const float* __restrict__ Wl4, const float* __restrict__ bl4,
                     float* __restrict__ out, int n) {
    __shared__ float sW2[1024];
    __shared__ float sWl1[1024];
    __shared__ float sb2[32], sbl1[32], sWl4[32];
    int tid = threadIdx.x;
    for (int j = tid; j < 1024; j += blockDim.x) {
        sW2[j] = W2[j];
        sWl1[j] = Wl1[j];
    }
    if (tid < 32) { sb2[tid] = b2[tid]; sbl1[tid] = bl1[tid]; sWl4[tid] = Wl4[tid]; }
    __syncthreads();

    int gw = (blockIdx.x * blockDim.x + tid) >> 5;
    int lane = tid & 31;
    if (gw >= n) return;

    int s = lane >> 3;       // 4 edge slots
    int q = lane & 7;        // 8 float4 chunks = 32 dims
    int beg = d_off[gw], end = d_off[gw + 1];
    float dc = d_dinv[gw];
    const float4* h1f4 = (const float4*)d_h1;

    float4 a0 = make_float4(0.f, 0.f, 0.f, 0.f);
    float4 a1 = make_float4(0.f, 0.f, 0.f, 0.f);
    int i = beg + s;
    for (; i + 4 < end; i += 8) {
        int2 e0 = d_csr2[i];
        int2 e1 = d_csr2[i + 4];
        float4 v0 = h1f4[(size_t)e0.x * 8 + q];
        float4 v1 = h1f4[(size_t)e1.x * 8 + q];
        float n0 = __int_as_float(e0.y), n1 = __int_as_float(e1.y);
        a0.x += n0 * v0.x; a0.y += n0 * v0.y; a0.z += n0 * v0.z; a0.w += n0 * v0.w;
        a1.x += n1 * v1.x; a1.y += n1 * v1.y; a1.z += n1 * v1.z; a1.w += n1 * v1.w;
    }
    if (i < end) {
        int2 e0 = d_csr2[i];
        float4 v0 = h1f4[(size_t)e0.x * 8 + q];
        float n0 = __int_as_float(e0.y);
        a0.x += n0 * v0.x; a0.y += n0 * v0.y; a0.z += n0 * v0.z; a0.w += n0 * v0.w;
    }
    float4 acc = make_float4(a0.x + a1.x, a0.y + a1.y, a0.z + a1.z, a0.w + a1.w);

    // fold edge slots (bits 3,4)
#pragma unroll
    for (int m = 8; m <= 16; m <<= 1) {
        acc.x += __shfl_xor_sync(0xffffffffu, acc.x, m);
        acc.y += __shfl_xor_sync(0xffffffffu, acc.y, m);
        acc.z += __shfl_xor_sync(0xffffffffu, acc.z, m);
        acc.w += __shfl_xor_sync(0xffffffffu, acc.w, m);
    }
    // lane d takes comp d&3 of chunk d>>2
    int src = lane >> 2;
    float c0 = __shfl_sync(0xffffffffu, acc.x, src);
    float c1 = __shfl_sync(0xffffffffu, acc.y, src);
    float c2 = __shfl_sync(0xffffffffu, acc.z, src);
    float c3 = __shfl_sync(0xffffffffu, acc.w, src);
    int cc = lane & 3;
    float agg = (cc == 0) ? c0 : (cc == 1) ? c1 : (cc == 2) ? c2 : c3;

    float v = dc * agg + dc * dc * d_h1[(size_t)gw * 32 + lane];

    float a2 = sb2[lane];
#pragma unroll
    for (int k = 0; k < 32; k++)
        a2 += __shfl_sync(0xffffffffu, v, k) * sW2[k * 32 + lane];
    float h2 = fmaxf(a2, 0.f);

    float a3 = sbl1[lane];
#pragma unroll
    for (int k = 0; k < 32; k++)
        a3 += __shfl_sync(0xffffffffu, h2, k) * sWl1[k * 32 + lane];
    float h3 = fmaxf(a3, 0.f);

    float p = h3 * sWl4[lane];
#pragma unroll
    for (int o = 16; o > 0; o >>= 1) p += __shfl_xor_sync(0xffffffffu, p, o);
    if (lane == 0) out[gw] = p + bl4[0];
}

// ---------------------------------------------------------------------------
extern "C" void kernel_launch(void* const* d_in, const int* in_sizes, int n_in,
                              void* d_out, int out_size) {
    // Runtime input resolution by element count.
    const float* x = 0; const int* ei = 0;
    const float *W1 = 0, *b1 = 0, *W2 = 0, *b2 = 0, *Wl1 = 0, *bl1 = 0, *Wl4 = 0, *bl4 = 0;

    bool alpha = (n_in > 0 && in_sizes[0] == 512);  // alphabetical puts W1 first
    int n1024 = 0, n32 = 0;
    for (int i = 0; i < n_in; i++) {
        int s = in_sizes[i];
        const void* p = d_in[i];
        if (s == 1600000)      x  = (const float*)p;
        else if (s == 6400000) ei = (const int*)p;
        else if (s == 512)     W1 = (const float*)p;
        else if (s == 1)       bl4 = (const float*)p;
        else if (s == 1024) {
            if (n1024 == 0) W2 = (const float*)p; else Wl1 = (const float*)p;
            n1024++;
        } else if (s == 32) {
            if (alpha) {
                if      (n32 == 0) Wl4 = (const float*)p;
                else if (n32 == 1) b1  = (const float*)p;
                else if (n32 == 2) b2  = (const float*)p;
                else               bl1 = (const float*)p;
            } else {
                if      (n32 == 0) b1  = (const float*)p;
                else if (n32 == 1) b2  = (const float*)p;
                else if (n32 == 2) bl1 = (const float*)p;
                else               Wl4 = (const float*)p;
            }
            n32++;
        }
    }
    float* out = (float*)d_out;

    int n = NN;
    int E = NE;
    int E4 = E / 4;

    const int TB = 256;
    int nodeBlocks = (n + TB - 1) / TB;
    int e4Blocks = (E4 + TB - 1) / TB;
    int warpNodeBlocks = (n * 32 + TB - 1) / TB;

    const int4* eir4 = (const int4*)ei;             // rows half
    const int4* eic4 = (const int4*)(ei + E);       // cols half

    k_deg<<<e4Blocks, TB>>>(eic4, E4, n);
    k_scanA<<<nodeBlocks, TB>>>(n);
    k_scanC<<<nodeBlocks, TB>>>(n, E);
    k_fill<<<e4Blocks, TB>>>(eir4, eic4, E4, n);
    k_l1<<<warpNodeBlocks, TB>>>((const float4*)x, x, W1, b1, n);
    k_l2<<<warpNodeBlocks, TB>>>(W2, b2, Wl1, bl1, Wl4, bl4, out, n);
}

// round 13
// speedup vs baseline: 1.3584x; 1.0668x over previous
#include <cuda_runtime.h>
#include <cuda_bf16.h>

#define NN 100000
#define NE 3200000
#define NBLK ((NN + 255) / 256)   // 391 scan blocks

// Scratch (static __device__ allocations — zero-init at load; scanA re-zeroes
// d_cnt each replay so the graph is replay-clean without a memset launch)
__device__ int   d_cnt[NN];        // in-degree counts (no self loop)
__device__ float d_dinv[NN];       // rsqrt(deg+1)
__device__ int   d_off[NN + 1];    // CSR offsets by col
__device__ int   d_cur[NN];        // fill cursors
__device__ int   d_bsum[NBLK];     // scan block sums
__device__ int   d_csr[NE];        // row ids grouped by col (4B/edge)
__device__ float d_xs[NN * 16];    // xs = dinv * x   (pre-scaled features)
__device__ float d_h1s[NN * 32];   // h1s = dinv * relu(layer1)

// ---------------------------------------------------------------------------
// histogram of col; 4 edges per thread via int4
__global__ void k_deg(const int4* __restrict__ eic4, int E4, int n) {
    int e = blockIdx.x * blockDim.x + threadIdx.x;
    if (e >= E4) return;
    int4 c = eic4[e];
    if ((unsigned)c.x >= (unsigned)n) c.x = 0;
    if ((unsigned)c.y >= (unsigned)n) c.y = 0;
    if ((unsigned)c.z >= (unsigned)n) c.z = 0;
    if ((unsigned)c.w >= (unsigned)n) c.w = 0;
    atomicAdd(&d_cnt[c.x], 1);
    atomicAdd(&d_cnt[c.y], 1);
    atomicAdd(&d_cnt[c.z], 1);
    atomicAdd(&d_cnt[c.w], 1);
}

// ---- per-block exclusive scan + block sums; zeroes d_cnt for next replay ----
__global__ void k_scanA(int n) {
    __shared__ int ws[8];
    int t = threadIdx.x;
    int i = blockIdx.x * 256 + t;
    int lane = t & 31, w = t >> 5;
    int v = 0;
    if (i < n) {
        v = d_cnt[i];
        d_cnt[i] = 0;                        // replay-clean without memset
    }
    int s = v;
#pragma unroll
    for (int o = 1; o < 32; o <<= 1) {
        int a = __shfl_up_sync(0xffffffffu, s, o);
        if (lane >= o) s += a;
    }
    if (lane == 31) ws[w] = s;
    __syncthreads();
    if (t < 8) {
        int a = ws[t];
#pragma unroll
        for (int o = 1; o < 8; o <<= 1) {
            int b = __shfl_up_sync(0xffu, a, o);
            if (t >= o) a += b;
        }
        ws[t] = a;
    }
    __syncthreads();
    int base = w ? ws[w - 1] : 0;
    int incl = base + s;
    if (i < n) {
        d_off[i] = incl - v;                 // exclusive within block
        d_dinv[i] = rsqrtf((float)v + 1.0f); // fused dinv
    }
    if (t == 255) d_bsum[blockIdx.x] = incl;
}

// finalize offsets (redundant block-sum reduction, smem broadcast) + xs = dinv*x
__global__ void k_scanC(const float4* __restrict__ x4, int n, int E) {
    __shared__ int red[8];
    __shared__ int sbase;
    int t = threadIdx.x;
    int bid = blockIdx.x;
    int lane = t & 31, w = t >> 5;

    int partial = 0;
    for (int j = t; j < bid; j += 256) partial += d_bsum[j];
#pragma unroll
    for (int o = 16; o > 0; o >>= 1)
        partial += __shfl_xor_sync(0xffffffffu, partial, o);
    if (lane == 0) red[w] = partial;
    __syncthreads();
    if (t == 0) {
        int b = 0;
#pragma unroll
        for (int j = 0; j < 8; j++) b += red[j];
        sbase = b;
    }
    __syncthreads();
    int base = sbase;

    int i = bid * 256 + t;
    if (i < n) {
        int o = d_off[i] + base;
        d_off[i] = o;
        d_cur[i] = o;
        float di = d_dinv[i];
        float4* xs4 = (float4*)(d_xs + (size_t)i * 16);
#pragma unroll
        for (int j = 0; j < 4; j++) {
            float4 a = x4[(size_t)i * 4 + j];
            xs4[j] = make_float4(di * a.x, di * a.y, di * a.z, di * a.w);
        }
    }
    if (i == 0) d_off[n] = E;
}

// counting-sort fill, 4 edges per thread; single 4B scattered store per edge
__global__ void k_fill(const int4* __restrict__ eir4,
                       const int4* __restrict__ eic4, int E4, int n) {
    int e = blockIdx.x * blockDim.x + threadIdx.x;
    if (e >= E4) return;
    int4 r = eir4[e];
    int4 c = eic4[e];
    if ((unsigned)r.x >= (unsigned)n) r.x = 0;
    if ((unsigned)r.y >= (unsigned)n) r.y = 0;
    if ((unsigned)r.z >= (unsigned)n) r.z = 0;
    if ((unsigned)r.w >= (unsigned)n) r.w = 0;
    if ((unsigned)c.x >= (unsigned)n) c.x = 0;
    if ((unsigned)c.y >= (unsigned)n) c.y = 0;
    if ((unsigned)c.z >= (unsigned)n) c.z = 0;
    if ((unsigned)c.w >= (unsigned)n) c.w = 0;
    int p0 = atomicAdd(&d_cur[c.x], 1);
    int p1 = atomicAdd(&d_cur[c.y], 1);
    int p2 = atomicAdd(&d_cur[c.z], 1);
    int p3 = atomicAdd(&d_cur[c.w], 1);
    d_csr[p0] = r.x;
    d_csr[p1] = r.y;
    d_csr[p2] = r.z;
    d_csr[p3] = r.w;
}

// ---------------------------------------------------------------------------
// Fused layer 1: aggregate xs (16 dims, pure sum) + GEMV 16->32 + ReLU,
// writes h1s = dinv * relu(...).
// warp/node; lane = (edge slot s = lane>>2) x (float4 chunk q = lane&3)
// software-pipelined 2 chains -> 16 edges in flight per warp
__global__ void k_l1(const float* __restrict__ W1,
                     const float* __restrict__ b1, int n) {
    __shared__ float sW[16 * 32];
    __shared__ float sb[32];
    int tid = threadIdx.x;
    for (int j = tid; j < 512; j += blockDim.x) sW[j] = W1[j];
    if (tid < 32) sb[tid] = b1[tid];
    __syncthreads();

    int gw = (blockIdx.x * blockDim.x + tid) >> 5;
    int lane = tid & 31;
    if (gw >= n) return;

    int s = lane >> 2;       // 8 edge slots
    int q = lane & 3;        // 4 float4 chunks = 16 dims
    int beg = d_off[gw], end = d_off[gw + 1];
    float dc = d_dinv[gw];
    const float4* xs4 = (const float4*)d_xs;

    float4 a0 = make_float4(0.f, 0.f, 0.f, 0.f);
    float4 a1 = make_float4(0.f, 0.f, 0.f, 0.f);
    int i = beg + s;
    for (; i + 8 < end; i += 16) {
        int r0 = d_csr[i];
        int r1 = d_csr[i + 8];
        float4 v0 = xs4[(size_t)r0 * 4 + q];
        float4 v1 = xs4[(size_t)r1 * 4 + q];
        a0.x += v0.x; a0.y += v0.y; a0.z += v0.z; a0.w += v0.w;
        a1.x += v1.x; a1.y += v1.y; a1.z += v1.z; a1.w += v1.w;
    }
    if (i < end) {
        int r0 = d_csr[i];
        float4 v0 = xs4[(size_t)r0 * 4 + q];
        a0.x += v0.x; a0.y += v0.y; a0.z += v0.z; a0.w += v0.w;
    }
    float4 acc = make_float4(a0.x + a1.x, a0.y + a1.y, a0.z + a1.z, a0.w + a1.w);

    // fold edge slots (bits 2,3,4 of lane)
#pragma unroll
    for (int m = 4; m <= 16; m <<= 1) {
        acc.x += __shfl_xor_sync(0xffffffffu, acc.x, m);
        acc.y += __shfl_xor_sync(0xffffffffu, acc.y, m);
        acc.z += __shfl_xor_sync(0xffffffffu, acc.z, m);
        acc.w += __shfl_xor_sync(0xffffffffu, acc.w, m);
    }
    // redistribute: lane d (<16) takes comp d&3 of chunk d>>2
    int src = lane >> 2;
    float c0 = __shfl_sync(0xffffffffu, acc.x, src);
    float c1 = __shfl_sync(0xffffffffu, acc.y, src);
    float c2 = __shfl_sync(0xffffffffu, acc.z, src);
    float c3 = __shfl_sync(0xffffffffu, acc.w, src);
    int cc = lane & 3;
    float agg = (cc == 0) ? c0 : (cc == 1) ? c1 : (cc == 2) ? c2 : c3;

    float v = 0.f;
    if (lane < 16)
        v = dc * (agg + d_xs[(size_t)gw * 16 + lane]);   // + self loop (xs)

    float o = sb[lane];
#pragma unroll
    for (int k = 0; k < 16; k++)
        o += __shfl_sync(0xffffffffu, v, k) * sW[k * 32 + lane];
    d_h1s[(size_t)gw * 32 + lane] = dc * fmaxf(o, 0.f);  // pre-scaled output
}

// Fused layer 2 + MLP tail. warp/node; lane = (slot s = lane>>3) x (chunk q = lane&7)
// software-pipelined 2 chains -> 8 edges in flight per warp
__global__ void k_l2(const float* __restrict__ W2, const float* __restrict__ b2,
                     const float* __restrict__ Wl1, const float* __restrict__ bl1,
                     const float* __restrict__ Wl4, const float* __restrict__ bl4,
                     float* __restrict__ out, int n) {
    __shared__ float sW2[1024];
    __shared__ float sWl1[1024];
    __shared__ float sb2[32], sbl1[32], sWl4[32];
    int tid = threadIdx.x;
    for (int j = tid; j < 1024; j += blockDim.x) {
        sW2[j] = W2[j];
        sWl1[j] = Wl1[j];
    }
    if (tid < 32) { sb2[tid] = b2[tid]; sbl1[tid] = bl1[tid]; sWl4[tid] = Wl4[tid]; }
    __syncthreads();

    int gw = (blockIdx.x * blockDim.x + tid) >> 5;
    int lane = tid & 31;
    if (gw >= n) return;

    int s = lane >> 3;       // 4 edge slots
    int q = lane & 7;        // 8 float4 chunks = 32 dims
    int beg = d_off[gw], end = d_off[gw + 1];
    float dc = d_dinv[gw];
    const float4* h1s4 = (const float4*)d_h1s;

    float4 a0 = make_float4(0.f, 0.f, 0.f, 0.f);
    float4 a1 = make_float4(0.f, 0.f, 0.f, 0.f);
    int i = beg + s;
    for (; i + 4 < end; i += 8) {
        int r0 = d_csr[i];
        int r1 = d_csr[i + 4];
        float4 v0 = h1s4[(size_t)r0 * 8 + q];
        float4 v1 = h1s4[(size_t)r1 * 8 + q];
        a0.x += v0.x; a0.y += v0.y; a0.z += v0.z; a0.w += v0.w;
        a1.x += v1.x; a1.y += v1.y; a1.z += v1.z; a1.w += v1.w;
    }
    if (i < end) {
        int r0 = d_csr[i];
        float4 v0 = h1s4[(size_t)r0 * 8 + q];
        a0.x += v0.x; a0.y += v0.y; a0.z += v0.z; a0.w += v0.w;
    }
    float4 acc = make_float4(a0.x + a1.x, a0.y + a1.y, a0.z + a1.z, a0.w + a1.w);

    // fold edge slots (bits 3,4)
#pragma unroll
    for (int m = 8; m <= 16; m <<= 1) {
        acc.x += __shfl_xor_sync(0xffffffffu, acc.x, m);
        acc.y += __shfl_xor_sync(0xffffffffu, acc.y, m);
        acc.z += __shfl_xor_sync(0xffffffffu, acc.z, m);
        acc.w += __shfl_xor_sync(0xffffffffu, acc.w, m);
    }
    // lane d takes comp d&3 of chunk d>>2
    int src = lane >> 2;
    float c0 = __shfl_sync(0xffffffffu, acc.x, src);
    float c1 = __shfl_sync(0xffffffffu, acc.y, src);
    float c2 = __shfl_sync(0xffffffffu, acc.z, src);
    float c3 = __shfl_sync(0xffffffffu, acc.w, src);
    int cc = lane & 3;
    float agg = (cc == 0) ? c0 : (cc == 1) ? c1 : (cc == 2) ? c2 : c3;

    float v = dc * (agg + d_h1s[(size_t)gw * 32 + lane]);   // + self loop (h1s)

    float a2 = sb2[lane];
#pragma unroll
    for (int k = 0; k < 32; k++)
        a2 += __shfl_sync(0xffffffffu, v, k) * sW2[k * 32 + lane];
    float h2 = fmaxf(a2, 0.f);

    float a3 = sbl1[lane];
#pragma unroll
    for (int k = 0; k < 32; k++)
        a3 += __shfl_sync(0xffffffffu, h2, k) * sWl1[k * 32 + lane];
    float h3 = fmaxf(a3, 0.f);

    float p = h3 * sWl4[lane];
#pragma unroll
    for (int o = 16; o > 0; o >>= 1) p += __shfl_xor_sync(0xffffffffu, p, o);
    if (lane == 0) out[gw] = p + bl4[0];
}

// ---------------------------------------------------------------------------
extern "C" void kernel_launch(void* const* d_in, const int* in_sizes, int n_in,
                              void* d_out, int out_size) {
    // Runtime input resolution by element count.
    const float* x = 0; const int* ei = 0;
    const float *W1 = 0, *b1 = 0, *W2 = 0, *b2 = 0, *Wl1 = 0, *bl1 = 0, *Wl4 = 0, *bl4 = 0;

    bool alpha = (n_in > 0 && in_sizes[0] == 512);  // alphabetical puts W1 first
    int n1024 = 0, n32 = 0;
    for (int i = 0; i < n_in; i++) {
        int s = in_sizes[i];
        const void* p = d_in[i];
        if (s == 1600000)      x  = (const float*)p;
        else if (s == 6400000) ei = (const int*)p;
        else if (s == 512)     W1 = (const float*)p;
        else if (s == 1)       bl4 = (const float*)p;
        else if (s == 1024) {
            if (n1024 == 0) W2 = (const float*)p; else Wl1 = (const float*)p;
            n1024++;
        } else if (s == 32) {
            if (alpha) {
                if      (n32 == 0) Wl4 = (const float*)p;
                else if (n32 == 1) b1  = (const float*)p;
                else if (n32 == 2) b2  = (const float*)p;
                else               bl1 = (const float*)p;
            } else {
                if      (n32 == 0) b1  = (const float*)p;
                else if (n32 == 1) b2  = (const float*)p;
                else if (n32 == 2) bl1 = (const float*)p;
                else               Wl4 = (const float*)p;
            }
            n32++;
        }
    }
    float* out = (float*)d_out;

    int n = NN;
    int E = NE;
    int E4 = E / 4;

    const int TB = 256;
    int nodeBlocks = (n + TB - 1) / TB;
    int e4Blocks = (E4 + TB - 1) / TB;
    int warpNodeBlocks = (n * 32 + TB - 1) / TB;

    const int4* eir4 = (const int4*)ei;             // rows half
    const int4* eic4 = (const int4*)(ei + E);       // cols half

    k_deg<<<e4Blocks, TB>>>(eic4, E4, n);
    k_scanA<<<nodeBlocks, TB>>>(n);
    k_scanC<<<nodeBlocks, TB>>>((const float4*)x, n, E);
    k_fill<<<e4Blocks, TB>>>(eir4, eic4, E4, n);
    k_l1<<<warpNodeBlocks, TB>>>(W1, b1, n);
    k_l2<<<warpNodeBlocks, TB>>>(W2, b2, Wl1, bl1, Wl4, bl4, out, n);
}